// round 1
// baseline (speedup 1.0000x reference)
#include <cuda_runtime.h>

// PDELayer: 100 explicit diffusion steps on 48x48 grids, 8192 batches.
// u_{n+1}[r,c] = u[r,c] + alpha(r)*(u[r+1,c]+u[r-1,c]-2u) + beta(c)*(u[r,c+1]+u[r,c-1]-2u)
// Boundary (50x50 reflect pad of u0) is FIXED at initial reflected values for all steps.
//
// Design: 1 CTA per batch. blockDim (12,48): thread owns 4 contiguous cells of
// one row, kept in REGISTERS across all 100 steps. Per step: publish own 4 cells
// to shared (STS.128), sync, read up/down rows (2x LDS.128) + 2 lateral seam
// scalars, compute, sync. Boundary written to shared once, never rewritten.

#define NXY    48
#define SSTRIDE 52          // shared row stride (floats)
#define SOFF    3           // so interior col 1 lands 16B-aligned
#define NT     100

__global__ void __launch_bounds__(576, 3)
pde_kernel(const float* __restrict__ u0,
           const float* __restrict__ aw1, const float* __restrict__ aw2,
           const float* __restrict__ aw3, const float* __restrict__ bw1,
           const float* __restrict__ bw2, const float* __restrict__ bw3,
           float* __restrict__ out)
{
    __shared__ float sh[50 * SSTRIDE + SOFF + 8];   // padded 50x50 grid

    const int tx = threadIdx.x;       // 0..11  (column group)
    const int ty = threadIdx.y;       // 0..47  (grid row)
    const int b  = blockIdx.x;

    const float* g = u0  + (size_t)b * (NXY * NXY);
    float*       o = out + (size_t)b * (NXY * NXY);
    const float4* g4 = (const float4*)g;

    // ---- coefficients (match reference: linspace(0,1,48), /DX^2 with DX=1/48) ----
    const float TWO_PI = 6.283185307179586f;
    const float DT     = 1e-4f;
    const float scale  = DT * 2304.0f;        // DT / (1/48)^2
    const float inv47  = 1.0f / 47.0f;

    const float aa1 = fabsf(*aw1), aa2 = fabsf(*aw2), aa3 = fabsf(*aw3);
    const float bb1 = fabsf(*bw1), bb2 = fabsf(*bw2), bb3 = fabsf(*bw3);

    const float yv = (float)ty * inv47;
    const float alpha = 0.5f * scale * (aa1 + aa2 * sinf(TWO_PI * yv)
                                            + aa3 * cosf(TWO_PI * yv));

    const int ccol = 4 * tx;                  // grid col of v[0] (0..44)
    float bet[4], c0[4];
    #pragma unroll
    for (int k = 0; k < 4; k++) {
        float xv = (float)(ccol + k) * inv47;
        bet[k] = scale * (bb1 + bb2 * cosf(TWO_PI * xv) + bb3 * sinf(TWO_PI * xv));
        c0[k]  = 1.0f - 2.0f * alpha - 2.0f * bet[k];
    }

    // ---- load own 4 interior cells into registers ----
    float4 vv = g4[ty * 12 + tx];
    float v0 = vv.x, v1 = vv.y, v2 = vv.z, v3 = vv.w;

    // ---- fixed reflected boundary into shared (written once) ----
    // padded row 0  = u0 row 1 ; padded row 49 = u0 row 46
    // padded col 0  = u0 col 1 ; padded col 49 = u0 col 46
    if (ty == 0) {
        float4 t = g4[1 * 12 + tx];
        *(float4*)&sh[0 * SSTRIDE + SOFF + ccol + 1] = t;
    }
    if (ty == 1) {
        float4 t = g4[46 * 12 + tx];
        *(float4*)&sh[49 * SSTRIDE + SOFF + ccol + 1] = t;
    }
    if (tx == 0) sh[(ty + 1) * SSTRIDE + SOFF + 0]  = g[ty * NXY + 1];
    if (tx == 1) sh[(ty + 1) * SSTRIDE + SOFF + 49] = g[ty * NXY + 46];

    float* rowp = &sh[(ty + 1) * SSTRIDE + SOFF + ccol + 1];  // own cells (16B aligned)
    const float* upp = rowp - SSTRIDE;
    const float* dnp = rowp + SSTRIDE;

    // ---- time loop: centers in registers, halos via shared ----
    #pragma unroll 2
    for (int t = 0; t < NT; t++) {
        *(float4*)rowp = make_float4(v0, v1, v2, v3);
        __syncthreads();

        float4 up = *(const float4*)upp;
        float4 dn = *(const float4*)dnp;
        float  lf = rowp[-1];
        float  rt = rowp[4];

        float n0 = fmaf(alpha, up.x + dn.x, v0 * c0[0]);
        float n1 = fmaf(alpha, up.y + dn.y, v1 * c0[1]);
        float n2 = fmaf(alpha, up.z + dn.z, v2 * c0[2]);
        float n3 = fmaf(alpha, up.w + dn.w, v3 * c0[3]);
        n0 = fmaf(bet[0], lf + v1, n0);
        n1 = fmaf(bet[1], v0 + v2, n1);
        n2 = fmaf(bet[2], v1 + v3, n2);
        n3 = fmaf(bet[3], v2 + rt, n3);

        __syncthreads();
        v0 = n0; v1 = n1; v2 = n2; v3 = n3;
    }

    // ---- write result ----
    ((float4*)o)[ty * 12 + tx] = make_float4(v0, v1, v2, v3);
}

extern "C" void kernel_launch(void* const* d_in, const int* in_sizes, int n_in,
                              void* d_out, int out_size)
{
    const float* u0  = (const float*)d_in[0];
    const float* aw1 = (const float*)d_in[1];
    const float* aw2 = (const float*)d_in[2];
    const float* aw3 = (const float*)d_in[3];
    const float* bw1 = (const float*)d_in[4];
    const float* bw2 = (const float*)d_in[5];
    const float* bw3 = (const float*)d_in[6];
    float* out = (float*)d_out;

    int batches = in_sizes[0] / (NXY * NXY);
    dim3 blk(12, 48);
    pde_kernel<<<batches, blk>>>(u0, aw1, aw2, aw3, bw1, bw2, bw3, out);
}

// round 2
// speedup vs baseline: 2.3634x; 2.3634x over previous
#include <cuda_runtime.h>

// PDELayer: 100 diffusion steps, 48x48 grids, 8192 batches, frozen reflect boundary.
// Round 2: register-resident 6x6 blocks per thread, halo via warp shuffle,
// packed f32x2 FMA math. CTA = 64 threads (2 warps) = 1 batch.
// Warp layout: lane = 8*trow + tcol; tcol in 0..7 (6 cols each), trow 0..3 (6 rows each).
// Warp 0 = grid rows 0..23, warp 1 = rows 24..47. Seam exchanged via tiny smem buffer.

#define NXY 48
#define NT  100

// ---- packed f32x2 helpers (ptxas only emits FFMA2/FADD2 via explicit PTX) ----
static __forceinline__ __device__ float2 f2add(float2 a, float2 b) {
    float2 d;
    asm("{\n\t.reg .b64 ra,rb,rd;\n\t"
        "mov.b64 ra,{%2,%3};\n\tmov.b64 rb,{%4,%5};\n\t"
        "add.rn.f32x2 rd, ra, rb;\n\t"
        "mov.b64 {%0,%1}, rd;\n\t}"
        : "=f"(d.x), "=f"(d.y)
        : "f"(a.x), "f"(a.y), "f"(b.x), "f"(b.y));
    return d;
}
static __forceinline__ __device__ float2 f2fma(float2 a, float2 b, float2 c) {
    float2 d;
    asm("{\n\t.reg .b64 ra,rb,rc,rd;\n\t"
        "mov.b64 ra,{%2,%3};\n\tmov.b64 rb,{%4,%5};\n\tmov.b64 rc,{%6,%7};\n\t"
        "fma.rn.f32x2 rd, ra, rb, rc;\n\t"
        "mov.b64 {%0,%1}, rd;\n\t}"
        : "=f"(d.x), "=f"(d.y)
        : "f"(a.x), "f"(a.y), "f"(b.x), "f"(b.y), "f"(c.x), "f"(c.y));
    return d;
}
static __forceinline__ __device__ float2 shfl_up2(float2 v, int delta) {
    float2 r;
    r.x = __shfl_up_sync(0xffffffffu, v.x, delta);
    r.y = __shfl_up_sync(0xffffffffu, v.y, delta);
    return r;
}
static __forceinline__ __device__ float2 shfl_dn2(float2 v, int delta) {
    float2 r;
    r.x = __shfl_down_sync(0xffffffffu, v.x, delta);
    r.y = __shfl_down_sync(0xffffffffu, v.y, delta);
    return r;
}

__global__ void __launch_bounds__(64, 8)
pde_kernel(const float* __restrict__ u0,
           const float* __restrict__ aw1, const float* __restrict__ aw2,
           const float* __restrict__ aw3, const float* __restrict__ bw1,
           const float* __restrict__ bw2, const float* __restrict__ bw3,
           float* __restrict__ out)
{
    __shared__ float2 seamA[2][24];   // warp0 row 23 (bottom of gr==3)
    __shared__ float2 seamB[2][24];   // warp1 row 24 (top of gr==4)

    const int tid   = threadIdx.x;
    const int warp  = tid >> 5;
    const int lane  = tid & 31;
    const int tcol  = lane & 7;        // 0..7   -> cols 6*tcol..6*tcol+5
    const int trow  = lane >> 3;       // 0..3
    const int gr    = warp * 4 + trow; // 0..7   -> rows 6*gr..6*gr+5
    const int b     = blockIdx.x;

    const float2* g2 = (const float2*)(u0  + (size_t)b * (NXY * NXY));
    float2*       o2 = (float2*)      (out + (size_t)b * (NXY * NXY));

    // ---- coefficients ----
    const float TWO_PI = 6.283185307179586f;
    const float scale  = 1e-4f * 2304.0f;     // DT / DX^2
    const float inv47  = 1.0f / 47.0f;
    const float aa1 = fabsf(*aw1), aa2 = fabsf(*aw2), aa3 = fabsf(*aw3);
    const float bb1 = fabsf(*bw1), bb2 = fabsf(*bw2), bb3 = fabsf(*bw3);

    float2 a2[6];                     // alpha per local row (packed duplicate)
    #pragma unroll
    for (int r = 0; r < 6; r++) {
        float yv = (float)(6 * gr + r) * inv47;
        float al = 0.5f * scale * (aa1 + aa2 * sinf(TWO_PI * yv) + aa3 * cosf(TWO_PI * yv));
        a2[r] = make_float2(al, al);
    }
    float2 b2c[3];                    // beta per col pair
    #pragma unroll
    for (int p = 0; p < 3; p++) {
        float x0 = (float)(6 * tcol + 2 * p)     * inv47;
        float x1 = (float)(6 * tcol + 2 * p + 1) * inv47;
        b2c[p].x = scale * (bb1 + bb2 * cosf(TWO_PI * x0) + bb3 * sinf(TWO_PI * x0));
        b2c[p].y = scale * (bb1 + bb2 * cosf(TWO_PI * x1) + bb3 * sinf(TWO_PI * x1));
    }
    const float2 m2 = make_float2(-2.0f, -2.0f);

    // ---- load 6x6 block into registers ----
    float2 v[6][3];
    #pragma unroll
    for (int r = 0; r < 6; r++)
        #pragma unroll
        for (int p = 0; p < 3; p++)
            v[r][p] = g2[(6 * gr + r) * 24 + tcol * 3 + p];

    // ---- frozen reflected boundary = copies of own initial values ----
    // top edge (gr==0): padded row 0 = initial row 1 = own local row 1
    // bottom (gr==7):   padded row 49 = initial row 46 = own local row 4
    float2 fv[3];
    #pragma unroll
    for (int p = 0; p < 3; p++) fv[p] = (gr == 0) ? v[1][p] : v[4][p];
    // left edge (tcol==0): padded col 0 = initial col 1 = own local col 1 (= v[r][0].y)
    // right (tcol==7):     padded col 49 = initial col 46 = own local col 4 (= v[r][2].x)
    float fh[6];
    #pragma unroll
    for (int r = 0; r < 6; r++) fh[r] = (tcol == 0) ? v[r][0].y : v[r][2].x;

    const bool isTop = (gr == 0), isBot = (gr == 7);
    const bool sw0   = (gr == 3), sw1   = (gr == 4);   // seam writers/readers
    const bool isL   = (tcol == 0), isR = (tcol == 7);
    const int  sidx  = tcol * 3;

    // ---- time loop ----
    #pragma unroll 2
    for (int t = 0; t < NT; t++) {
        const int buf = t & 1;
        if (sw0) { seamA[buf][sidx] = v[5][0]; seamA[buf][sidx+1] = v[5][1]; seamA[buf][sidx+2] = v[5][2]; }
        if (sw1) { seamB[buf][sidx] = v[0][0]; seamB[buf][sidx+1] = v[0][1]; seamB[buf][sidx+2] = v[0][2]; }
        __syncthreads();

        // halos (read OLD state)
        float2 th[3], bh[3];
        #pragma unroll
        for (int p = 0; p < 3; p++) {
            float2 tu = shfl_up2(v[5][p], 8);
            float2 bd = shfl_dn2(v[0][p], 8);
            th[p] = isTop ? fv[p] : (sw1 ? seamA[buf][sidx + p] : tu);
            bh[p] = isBot ? fv[p] : (sw0 ? seamB[buf][sidx + p] : bd);
        }
        float lh[6], rh[6];
        #pragma unroll
        for (int r = 0; r < 6; r++) {
            float lu = __shfl_up_sync(0xffffffffu, v[r][2].y, 1);
            float rd = __shfl_down_sync(0xffffffffu, v[r][0].x, 1);
            lh[r] = isL ? fh[r] : lu;
            rh[r] = isR ? fh[r] : rd;
        }

        // compute: res = v + alpha*(up+dn-2v) + beta*(lf+rt-2v)
        float2 oldprev[3];
        #pragma unroll
        for (int p = 0; p < 3; p++) oldprev[p] = th[p];
        #pragma unroll
        for (int r = 0; r < 6; r++) {
            float x0 = v[r][0].x, x1 = v[r][0].y, x2 = v[r][1].x;
            float x3 = v[r][1].y, x4 = v[r][2].x, x5 = v[r][2].y;
            float s0 = lh[r] + x1, s1 = x0 + x2, s2 = x1 + x3;
            float s3 = x2 + x4,    s4 = x3 + x5, s5 = x4 + rh[r];
            float2 hs0 = make_float2(s0, s1);
            float2 hs1 = make_float2(s2, s3);
            float2 hs2 = make_float2(s4, s5);
            #pragma unroll
            for (int p = 0; p < 3; p++) {
                float2 dn = (r == 5) ? bh[p] : v[r + 1][p];
                float2 cur = v[r][p];
                float2 vt = f2add(oldprev[p], dn);        // up + dn
                vt = f2fma(m2, cur, vt);                  // up + dn - 2v
                float2 hs = (p == 0) ? hs0 : (p == 1) ? hs1 : hs2;
                hs = f2fma(m2, cur, hs);                  // lf + rt - 2v
                float2 res = f2fma(a2[r], vt, cur);       // v + a*vt
                res = f2fma(b2c[p], hs, res);             // + b*hs
                oldprev[p] = cur;
                v[r][p] = res;
            }
        }
    }

    // ---- store result ----
    #pragma unroll
    for (int r = 0; r < 6; r++)
        #pragma unroll
        for (int p = 0; p < 3; p++)
            o2[(6 * gr + r) * 24 + tcol * 3 + p] = v[r][p];
}

extern "C" void kernel_launch(void* const* d_in, const int* in_sizes, int n_in,
                              void* d_out, int out_size)
{
    const float* u0  = (const float*)d_in[0];
    int batches = in_sizes[0] / (NXY * NXY);
    pde_kernel<<<batches, 64>>>(u0,
        (const float*)d_in[1], (const float*)d_in[2], (const float*)d_in[3],
        (const float*)d_in[4], (const float*)d_in[5], (const float*)d_in[6],
        (float*)d_out);
}